// round 1
// baseline (speedup 1.0000x reference)
#include <cuda_runtime.h>

// 4D circular conv, kernel 3^4, on (b=4, ci=64, 16,16,16,16) -> (b, co=64, 16^4).
// out[b,co,t,y,z,w] = bias[co] + sum_{i,ci,dy,dz,dw} x[b,ci,(t+i-1)%16,(y+dy-1)%16,(z+dz-1)%16,(w+dw-1)%16]
//                                                   * W[i,co,ci,dy,dz,dw]
//
// Block = (b, t, y, co-group-of-16). 256 threads, each computes 4 co x 4 (z,w) outputs.
// Per ci-chunk (CC=2): stage x slab [CC][9 taps][256 zw] and weight slice [81][CC][16 co]
// in shared memory; inner loop is 16 FFMA per (tap, ci) with 4 conflict-free LDS + 1 LDS.128 bcast.

#define S4 4096          // 16*16*16 (t,y fixed -> 256 zw per (t,y))
#define POS 65536        // 16^4
#define CC 2

__global__ __launch_bounds__(256, 4) void conv4d_kernel(
    const float* __restrict__ x, const float* __restrict__ wt,
    const float* __restrict__ bias, float* __restrict__ out)
{
    __shared__ float xs[CC * 9 * 256];   // [ci][i*3+dy][zz*16+ww]
    __shared__ float ws[81 * CC * 16];   // [off][ci][co]

    const int bid = blockIdx.x;
    const int cog = bid & 3;           // co tile of 16
    const int y   = (bid >> 2) & 15;
    const int t   = (bid >> 6) & 15;
    const int b   = bid >> 10;

    const int tid = threadIdx.x;
    const int cg  = tid >> 6;          // 0..3 : co sub-group of 4
    const int pl  = tid & 63;
    const int wp  = pl & 15;           // w position (16 lanes -> 16 consecutive w)
    const int zb  = pl >> 4;           // 0..3 : z base; thread covers z = zb + 4j

    // Precomputed shared-mem offsets for the circular shifts
    int wdw[3];
#pragma unroll
    for (int dw = 0; dw < 3; dw++) wdw[dw] = (wp + dw + 15) & 15;
    int zrow[4][3];
#pragma unroll
    for (int j = 0; j < 4; j++)
#pragma unroll
        for (int dz = 0; dz < 3; dz++)
            zrow[j][dz] = ((zb + 4 * j + dz + 15) & 15) << 4;

    float acc[4][4];
#pragma unroll
    for (int q = 0; q < 4; q++)
#pragma unroll
        for (int j = 0; j < 4; j++) acc[q][j] = 0.f;

    const float* xb = x + (long long)b * (64 * POS);

    for (int cc = 0; cc < 64 / CC; cc++) {
        const int cbase = cc * CC;

        // ---- stage x: CC*9 rows of 256 contiguous floats (float4, coalesced) ----
        for (int k = tid; k < CC * 9 * 64; k += 256) {
            int r = k >> 6, c = k & 63;
            int ci = r / 9, iy = r - ci * 9;
            int i = iy / 3, dy = iy - i * 3;
            int tt = (t + i + 15) & 15;
            int yy = (y + dy + 15) & 15;
            const float4* src =
                (const float4*)(xb + (((cbase + ci) * 16 + tt) * 16 + yy) * 256);
            ((float4*)xs)[r * 64 + c] = src[c];
        }
        // ---- stage weights: [off][ci][co16] ----
        for (int k = tid; k < 81 * CC * 16; k += 256) {
            int off = k >> 5;          // CC*16 = 32
            int rem = k & 31;
            int ci = rem >> 4, co = rem & 15;
            int dw = off % 3, r3 = off / 3;
            int dz = r3 % 3, r9 = r3 / 3;
            int dy = r9 % 3, i = r9 / 3;
            ws[k] = wt[((i * 64 + cog * 16 + co) * 64 + cbase + ci) * 27
                       + dy * 9 + dz * 3 + dw];
        }
        __syncthreads();

        // ---- compute ----
#pragma unroll 1
        for (int iy = 0; iy < 9; iy++) {
#pragma unroll
            for (int ci = 0; ci < CC; ci++) {
                const float* xr = xs + (ci * 9 + iy) * 256;
#pragma unroll
                for (int dz = 0; dz < 3; dz++) {
#pragma unroll
                    for (int dw = 0; dw < 3; dw++) {
                        const int off = (iy * 3 + dz) * 3 + dw;
                        float4 wv =
                            *(const float4*)&ws[off * 32 + ci * 16 + cg * 4];
                        float wq[4] = {wv.x, wv.y, wv.z, wv.w};
                        float xv[4];
#pragma unroll
                        for (int j = 0; j < 4; j++)
                            xv[j] = xr[zrow[j][dz] + wdw[dw]];
#pragma unroll
                        for (int q = 0; q < 4; q++)
#pragma unroll
                            for (int j = 0; j < 4; j++)
                                acc[q][j] += wq[q] * xv[j];
                    }
                }
            }
        }
        __syncthreads();
    }

    // ---- epilogue: add bias, write out ----
    const int co0 = cog * 16 + cg * 4;
    long long ob = ((long long)b * 64 + co0) * POS + (t * 16 + y) * 256;
#pragma unroll
    for (int q = 0; q < 4; q++) {
        float bv = bias[co0 + q];
#pragma unroll
        for (int j = 0; j < 4; j++)
            out[ob + (long long)q * POS + (zb + 4 * j) * 16 + wp] = acc[q][j] + bv;
    }
}

extern "C" void kernel_launch(void* const* d_in, const int* in_sizes, int n_in,
                              void* d_out, int out_size) {
    const float* x    = (const float*)d_in[0];
    const float* w    = (const float*)d_in[1];
    const float* bias = (const float*)d_in[2];
    float* out        = (float*)d_out;
    conv4d_kernel<<<4096, 256>>>(x, w, bias, out);
}

// round 2
// speedup vs baseline: 1.0017x; 1.0017x over previous
#include <cuda_runtime.h>

// 4D circular conv, kernel 3^4, on (b=4, ci=64, 16,16,16,16) -> (b, co=64, 16^4).
// out[b,co,t,y,z,w] = bias[co] + sum_{i,ci,dy,dz,dw} x[b,ci,(t+i-1)%16,(y+dy-1)%16,(z+dz-1)%16,(w+dw-1)%16]
//                                                   * W[i,co,ci,dy,dz,dw]
//
// Block = (b, t, y, co-group-of-16). 256 threads, each computes 4 co x 4 (z,w) outputs.
// Per ci-chunk (CC=2): stage x slab [CC][9 taps][256 zw] and weight slice [81][CC][16 co]
// in shared memory; inner loop is 16 FFMA per (tap, ci) with 4 conflict-free LDS + 1 LDS.128 bcast.

#define S4 4096          // 16*16*16 (t,y fixed -> 256 zw per (t,y))
#define POS 65536        // 16^4
#define CC 2

__global__ __launch_bounds__(256, 4) void conv4d_kernel(
    const float* __restrict__ x, const float* __restrict__ wt,
    const float* __restrict__ bias, float* __restrict__ out)
{
    __shared__ float xs[CC * 9 * 256];   // [ci][i*3+dy][zz*16+ww]
    __shared__ float ws[81 * CC * 16];   // [off][ci][co]

    const int bid = blockIdx.x;
    const int cog = bid & 3;           // co tile of 16
    const int y   = (bid >> 2) & 15;
    const int t   = (bid >> 6) & 15;
    const int b   = bid >> 10;

    const int tid = threadIdx.x;
    const int cg  = tid >> 6;          // 0..3 : co sub-group of 4
    const int pl  = tid & 63;
    const int wp  = pl & 15;           // w position (16 lanes -> 16 consecutive w)
    const int zb  = pl >> 4;           // 0..3 : z base; thread covers z = zb + 4j

    // Precomputed shared-mem offsets for the circular shifts
    int wdw[3];
#pragma unroll
    for (int dw = 0; dw < 3; dw++) wdw[dw] = (wp + dw + 15) & 15;
    int zrow[4][3];
#pragma unroll
    for (int j = 0; j < 4; j++)
#pragma unroll
        for (int dz = 0; dz < 3; dz++)
            zrow[j][dz] = ((zb + 4 * j + dz + 15) & 15) << 4;

    float acc[4][4];
#pragma unroll
    for (int q = 0; q < 4; q++)
#pragma unroll
        for (int j = 0; j < 4; j++) acc[q][j] = 0.f;

    const float* xb = x + (long long)b * (64 * POS);

    for (int cc = 0; cc < 64 / CC; cc++) {
        const int cbase = cc * CC;

        // ---- stage x: CC*9 rows of 256 contiguous floats (float4, coalesced) ----
        for (int k = tid; k < CC * 9 * 64; k += 256) {
            int r = k >> 6, c = k & 63;
            int ci = r / 9, iy = r - ci * 9;
            int i = iy / 3, dy = iy - i * 3;
            int tt = (t + i + 15) & 15;
            int yy = (y + dy + 15) & 15;
            const float4* src =
                (const float4*)(xb + (((cbase + ci) * 16 + tt) * 16 + yy) * 256);
            ((float4*)xs)[r * 64 + c] = src[c];
        }
        // ---- stage weights: [off][ci][co16] ----
        for (int k = tid; k < 81 * CC * 16; k += 256) {
            int off = k >> 5;          // CC*16 = 32
            int rem = k & 31;
            int ci = rem >> 4, co = rem & 15;
            int dw = off % 3, r3 = off / 3;
            int dz = r3 % 3, r9 = r3 / 3;
            int dy = r9 % 3, i = r9 / 3;
            ws[k] = wt[((i * 64 + cog * 16 + co) * 64 + cbase + ci) * 27
                       + dy * 9 + dz * 3 + dw];
        }
        __syncthreads();

        // ---- compute ----
#pragma unroll 1
        for (int iy = 0; iy < 9; iy++) {
#pragma unroll
            for (int ci = 0; ci < CC; ci++) {
                const float* xr = xs + (ci * 9 + iy) * 256;
#pragma unroll
                for (int dz = 0; dz < 3; dz++) {
#pragma unroll
                    for (int dw = 0; dw < 3; dw++) {
                        const int off = (iy * 3 + dz) * 3 + dw;
                        float4 wv =
                            *(const float4*)&ws[off * 32 + ci * 16 + cg * 4];
                        float wq[4] = {wv.x, wv.y, wv.z, wv.w};
                        float xv[4];
#pragma unroll
                        for (int j = 0; j < 4; j++)
                            xv[j] = xr[zrow[j][dz] + wdw[dw]];
#pragma unroll
                        for (int q = 0; q < 4; q++)
#pragma unroll
                            for (int j = 0; j < 4; j++)
                                acc[q][j] += wq[q] * xv[j];
                    }
                }
            }
        }
        __syncthreads();
    }

    // ---- epilogue: add bias, write out ----
    const int co0 = cog * 16 + cg * 4;
    long long ob = ((long long)b * 64 + co0) * POS + (t * 16 + y) * 256;
#pragma unroll
    for (int q = 0; q < 4; q++) {
        float bv = bias[co0 + q];
#pragma unroll
        for (int j = 0; j < 4; j++)
            out[ob + (long long)q * POS + (zb + 4 * j) * 16 + wp] = acc[q][j] + bv;
    }
}

extern "C" void kernel_launch(void* const* d_in, const int* in_sizes, int n_in,
                              void* d_out, int out_size) {
    const float* x    = (const float*)d_in[0];
    const float* w    = (const float*)d_in[1];
    const float* bias = (const float*)d_in[2];
    float* out        = (float*)d_out;
    conv4d_kernel<<<4096, 256>>>(x, w, bias, out);
}

// round 3
// speedup vs baseline: 1.0021x; 1.0003x over previous
#include <cuda_runtime.h>

// 4D circular conv, kernel 3^4, on (b=4, ci=64, 16,16,16,16) -> (b, co=64, 16^4).
// out[b,co,t,y,z,w] = bias[co] + sum_{i,ci,dy,dz,dw} x[b,ci,(t+i-1)%16,(y+dy-1)%16,(z+dz-1)%16,(w+dw-1)%16]
//                                                   * W[i,co,ci,dy,dz,dw]
//
// Block = (b, t, y, co-group-of-16). 256 threads, each computes 4 co x 4 (z,w) outputs.
// Per ci-chunk (CC=2): stage x slab [CC][9 taps][256 zw] and weight slice [81][CC][16 co]
// in shared memory; inner loop is 16 FFMA per (tap, ci) with 4 conflict-free LDS + 1 LDS.128 bcast.

#define S4 4096          // 16*16*16 (t,y fixed -> 256 zw per (t,y))
#define POS 65536        // 16^4
#define CC 2

__global__ __launch_bounds__(256, 4) void conv4d_kernel(
    const float* __restrict__ x, const float* __restrict__ wt,
    const float* __restrict__ bias, float* __restrict__ out)
{
    __shared__ float xs[CC * 9 * 256];   // [ci][i*3+dy][zz*16+ww]
    __shared__ float ws[81 * CC * 16];   // [off][ci][co]

    const int bid = blockIdx.x;
    const int cog = bid & 3;           // co tile of 16
    const int y   = (bid >> 2) & 15;
    const int t   = (bid >> 6) & 15;
    const int b   = bid >> 10;

    const int tid = threadIdx.x;
    const int cg  = tid >> 6;          // 0..3 : co sub-group of 4
    const int pl  = tid & 63;
    const int wp  = pl & 15;           // w position (16 lanes -> 16 consecutive w)
    const int zb  = pl >> 4;           // 0..3 : z base; thread covers z = zb + 4j

    // Precomputed shared-mem offsets for the circular shifts
    int wdw[3];
#pragma unroll
    for (int dw = 0; dw < 3; dw++) wdw[dw] = (wp + dw + 15) & 15;
    int zrow[4][3];
#pragma unroll
    for (int j = 0; j < 4; j++)
#pragma unroll
        for (int dz = 0; dz < 3; dz++)
            zrow[j][dz] = ((zb + 4 * j + dz + 15) & 15) << 4;

    float acc[4][4];
#pragma unroll
    for (int q = 0; q < 4; q++)
#pragma unroll
        for (int j = 0; j < 4; j++) acc[q][j] = 0.f;

    const float* xb = x + (long long)b * (64 * POS);

    for (int cc = 0; cc < 64 / CC; cc++) {
        const int cbase = cc * CC;

        // ---- stage x: CC*9 rows of 256 contiguous floats (float4, coalesced) ----
        for (int k = tid; k < CC * 9 * 64; k += 256) {
            int r = k >> 6, c = k & 63;
            int ci = r / 9, iy = r - ci * 9;
            int i = iy / 3, dy = iy - i * 3;
            int tt = (t + i + 15) & 15;
            int yy = (y + dy + 15) & 15;
            const float4* src =
                (const float4*)(xb + (((cbase + ci) * 16 + tt) * 16 + yy) * 256);
            ((float4*)xs)[r * 64 + c] = src[c];
        }
        // ---- stage weights: [off][ci][co16] ----
        for (int k = tid; k < 81 * CC * 16; k += 256) {
            int off = k >> 5;          // CC*16 = 32
            int rem = k & 31;
            int ci = rem >> 4, co = rem & 15;
            int dw = off % 3, r3 = off / 3;
            int dz = r3 % 3, r9 = r3 / 3;
            int dy = r9 % 3, i = r9 / 3;
            ws[k] = wt[((i * 64 + cog * 16 + co) * 64 + cbase + ci) * 27
                       + dy * 9 + dz * 3 + dw];
        }
        __syncthreads();

        // ---- compute ----
#pragma unroll 1
        for (int iy = 0; iy < 9; iy++) {
#pragma unroll
            for (int ci = 0; ci < CC; ci++) {
                const float* xr = xs + (ci * 9 + iy) * 256;
#pragma unroll
                for (int dz = 0; dz < 3; dz++) {
#pragma unroll
                    for (int dw = 0; dw < 3; dw++) {
                        const int off = (iy * 3 + dz) * 3 + dw;
                        float4 wv =
                            *(const float4*)&ws[off * 32 + ci * 16 + cg * 4];
                        float wq[4] = {wv.x, wv.y, wv.z, wv.w};
                        float xv[4];
#pragma unroll
                        for (int j = 0; j < 4; j++)
                            xv[j] = xr[zrow[j][dz] + wdw[dw]];
#pragma unroll
                        for (int q = 0; q < 4; q++)
#pragma unroll
                            for (int j = 0; j < 4; j++)
                                acc[q][j] += wq[q] * xv[j];
                    }
                }
            }
        }
        __syncthreads();
    }

    // ---- epilogue: add bias, write out ----
    const int co0 = cog * 16 + cg * 4;
    long long ob = ((long long)b * 64 + co0) * POS + (t * 16 + y) * 256;
#pragma unroll
    for (int q = 0; q < 4; q++) {
        float bv = bias[co0 + q];
#pragma unroll
        for (int j = 0; j < 4; j++)
            out[ob + (long long)q * POS + (zb + 4 * j) * 16 + wp] = acc[q][j] + bv;
    }
}

extern "C" void kernel_launch(void* const* d_in, const int* in_sizes, int n_in,
                              void* d_out, int out_size) {
    const float* x    = (const float*)d_in[0];
    const float* w    = (const float*)d_in[1];
    const float* bias = (const float*)d_in[2];
    float* out        = (float*)d_out;
    conv4d_kernel<<<4096, 256>>>(x, w, bias, out);
}

// round 5
// speedup vs baseline: 2.7441x; 2.7385x over previous
#include <cuda_runtime.h>
#include <cuda_bf16.h>
#include <cstdint>

// ============================================================================
// 4D circular conv (3^4), implicit GEMM on legacy tensor-core mma.sync (bf16
// hi/lo 3-chain for fp32-grade accuracy). tcgen05 unavailable: harness PTX
// targets sm_103 (no 'a'), which rejects all tcgen05/TMEM instructions.
//
// Per block (b,t,y,h): D[M=128 pos (8z x 16w), N=64 co] in registers.
// K folds (ci-chunk=32, dw=3) -> 96 per phase; dz = row offset into z-haloed
// A slab; 18 phases = 9 (i,dy) x 2 ci-chunks.
// A in SMEM m-major [k][m] (ldmatrix.trans), B [co][k] (ldmatrix non-trans).
// ============================================================================

#define A_STRIDE 336      // bytes per k-row (168 bf16; 160 used) -> conflict-free
#define A_SIZE   32256    // 96 * 336
#define OFF_A_LO 32256
#define OFF_B    64512
#define B_STRIDE 208      // bytes per co-row (104 bf16; 96 used) -> conflict-free
#define B_BLK    13312    // 64 * 208
#define SMEM_BYTES 144384 // OFF_B + 6*B_BLK
#define POS 65536

__device__ __forceinline__ uint32_t smem_u32(const void* p) {
    uint32_t a;
    asm("{ .reg .u64 t; cvta.to.shared.u64 t, %1; cvt.u32.u64 %0, t; }" : "=r"(a) : "l"(p));
    return a;
}

#define LDSM4(R, ADDR) \
    asm volatile("ldmatrix.sync.aligned.m8n8.x4.shared.b16 {%0,%1,%2,%3}, [%4];" \
        : "=r"((R)[0]), "=r"((R)[1]), "=r"((R)[2]), "=r"((R)[3]) : "r"(ADDR))
#define LDSM4T(R, ADDR) \
    asm volatile("ldmatrix.sync.aligned.m8n8.x4.trans.shared.b16 {%0,%1,%2,%3}, [%4];" \
        : "=r"((R)[0]), "=r"((R)[1]), "=r"((R)[2]), "=r"((R)[3]) : "r"(ADDR))
#define MMA16816(D, A, B0, B1) \
    asm volatile("mma.sync.aligned.m16n8k16.row.col.f32.bf16.bf16.f32 " \
        "{%0,%1,%2,%3}, {%4,%5,%6,%7}, {%8,%9}, {%0,%1,%2,%3};" \
        : "+f"((D)[0]), "+f"((D)[1]), "+f"((D)[2]), "+f"((D)[3]) \
        : "r"((A)[0]), "r"((A)[1]), "r"((A)[2]), "r"((A)[3]), "r"(B0), "r"(B1))

// ---- weight images: exact padded SMEM layout [co][k], per (tap,ver,chunk) ---
__device__ __align__(16) __nv_bfloat16 g_B[108 * 6656];   // 6656 = 64*104

__global__ void prep_B(const float* __restrict__ wt) {
    int nb = blockIdx.x;                       // (((i*3+dy)*3+dz)*2+ver)*2+chunk
    int chunk = nb & 1, ver = (nb >> 1) & 1, tap = nb >> 2;
    int dz = tap % 3, dy = (tap / 3) % 3, i = tap / 9;
    for (int e = threadIdx.x; e < 64 * 96; e += blockDim.x) {
        int co = e / 96, k = e - co * 96;      // k = cil*3 + dw
        int cil = k / 3, dw = k - cil * 3;
        int ci = chunk * 32 + cil;
        float w = wt[((i * 64 + co) * 64 + ci) * 27 + dy * 9 + dz * 3 + dw];
        __nv_bfloat16 hb = __float2bfloat16(w);
        __nv_bfloat16 vb = ver ? __float2bfloat16(w - __bfloat162float(hb)) : hb;
        g_B[nb * 6656 + co * 104 + k] = vb;
    }
}

// ---- main kernel ------------------------------------------------------------
__global__ __launch_bounds__(256, 1) void conv4d_mma(
    const float* __restrict__ x, const float* __restrict__ bias,
    float* __restrict__ out)
{
    extern __shared__ __align__(16) char smem[];
    const uint32_t sb = smem_u32(smem);
    const int tid = threadIdx.x;
    const int l = tid & 31, wid = tid >> 5;
    const int wm = wid & 3, wn = wid >> 2;     // warp tile: (wm*32 M, wn*32 N)

    const int bid = blockIdx.x;
    const int h = bid & 1;
    const int y = (bid >> 1) & 15;
    const int t = (bid >> 5) & 15;
    const int b = bid >> 9;

    // ldmatrix per-lane address offsets (mat0..3 = lane groups of 8)
    const uint32_t aoff = ((l & 7) + ((l >> 4) & 1) * 8) * A_STRIDE + ((l >> 3) & 1) * 16;
    const uint32_t boff = ((l & 7) + ((l >> 4) & 1) * 8) * B_STRIDE + ((l >> 3) & 1) * 16;

    float d[2][4][4];
#pragma unroll
    for (int mi = 0; mi < 2; mi++)
#pragma unroll
        for (int nj = 0; nj < 4; nj++)
#pragma unroll
            for (int e = 0; e < 4; e++) d[mi][nj][e] = 0.f;

#pragma unroll 1
    for (int p = 0; p < 18; p++) {
        const int chunk = p & 1;
        const int idy9 = p >> 1;
        const int i = idy9 / 3, dy = idy9 - i * 3;
        const int tt = (t + i + 15) & 15;
        const int yy = (y + dy + 15) & 15;

        if (p > 0) __syncthreads();            // prior compute done reading SMEM

        // ---- stage A: 320 tasks (cil 32 x halo-z 10); hi/lo, 3 w-rotations ----
        for (int task = tid; task < 320; task += 256) {
            int cil = task / 10, r0 = task - cil * 10;
            int z_in = (8 * h + 15 + r0) & 15;
            const float4* src = (const float4*)(x +
                ((((b * 64 + chunk * 32 + cil) * 16 + tt) * 16 + yy) << 8) + z_in * 16);
            float v[16];
            *(float4*)(v)      = src[0];
            *(float4*)(v + 4)  = src[1];
            *(float4*)(v + 8)  = src[2];
            *(float4*)(v + 12) = src[3];
            uint32_t hp[8], lp[8];
#pragma unroll
            for (int j = 0; j < 8; j++) {
                float v0 = v[2 * j], v1 = v[2 * j + 1];
                __nv_bfloat16 h0 = __float2bfloat16(v0), h1 = __float2bfloat16(v1);
                __nv_bfloat16 l0 = __float2bfloat16(v0 - __bfloat162float(h0));
                __nv_bfloat16 l1 = __float2bfloat16(v1 - __bfloat162float(h1));
                hp[j] = (uint32_t)__bfloat16_as_ushort(h0) |
                        ((uint32_t)__bfloat16_as_ushort(h1) << 16);
                lp[j] = (uint32_t)__bfloat16_as_ushort(l0) |
                        ((uint32_t)__bfloat16_as_ushort(l1) << 16);
            }
            uint32_t h0r[8], h2r[8], l0r[8], l2r[8];   // rotations for dw=0 / dw=2
#pragma unroll
            for (int j = 0; j < 8; j++) {
                h0r[j] = __byte_perm(hp[(j + 7) & 7], hp[j], 0x5432);
                h2r[j] = __byte_perm(hp[j], hp[(j + 1) & 7], 0x5432);
                l0r[j] = __byte_perm(lp[(j + 7) & 7], lp[j], 0x5432);
                l2r[j] = __byte_perm(lp[j], lp[(j + 1) & 7], 0x5432);
            }
            char* bh = smem + (cil * 3) * A_STRIDE + r0 * 32;        // hi, k=cil*3
            char* bl = bh + OFF_A_LO;
            *(uint4*)(bh)                     = make_uint4(h0r[0], h0r[1], h0r[2], h0r[3]);
            *(uint4*)(bh + 16)                = make_uint4(h0r[4], h0r[5], h0r[6], h0r[7]);
            *(uint4*)(bh + A_STRIDE)          = make_uint4(hp[0], hp[1], hp[2], hp[3]);
            *(uint4*)(bh + A_STRIDE + 16)     = make_uint4(hp[4], hp[5], hp[6], hp[7]);
            *(uint4*)(bh + 2 * A_STRIDE)      = make_uint4(h2r[0], h2r[1], h2r[2], h2r[3]);
            *(uint4*)(bh + 2 * A_STRIDE + 16) = make_uint4(h2r[4], h2r[5], h2r[6], h2r[7]);
            *(uint4*)(bl)                     = make_uint4(l0r[0], l0r[1], l0r[2], l0r[3]);
            *(uint4*)(bl + 16)                = make_uint4(l0r[4], l0r[5], l0r[6], l0r[7]);
            *(uint4*)(bl + A_STRIDE)          = make_uint4(lp[0], lp[1], lp[2], lp[3]);
            *(uint4*)(bl + A_STRIDE + 16)     = make_uint4(lp[4], lp[5], lp[6], lp[7]);
            *(uint4*)(bl + 2 * A_STRIDE)      = make_uint4(l2r[0], l2r[1], l2r[2], l2r[3]);
            *(uint4*)(bl + 2 * A_STRIDE + 16) = make_uint4(l2r[4], l2r[5], l2r[6], l2r[7]);
        }

        // ---- stage B: 6 blocks x 13312B straight copy (slot = dz*2 + ver) ----
        {
            const int tapb = idy9 * 3;
            for (int q = tid; q < 6 * 832; q += 256) {
                int s = q / 832, r = q - s * 832;
                int dz = s >> 1, ver = s & 1;
                int nb = ((tapb + dz) * 2 + ver) * 2 + chunk;
                ((uint4*)(smem + OFF_B + s * B_BLK))[r] =
                    ((const uint4*)((const char*)g_B + (size_t)nb * B_BLK))[r];
            }
        }
        __syncthreads();

        // ---- compute: 6 k-steps x 3 dz x 3 chains x (2m x 4n) mma ----
#pragma unroll 1
        for (int ks = 0; ks < 6; ks++) {
#pragma unroll
            for (int dz = 0; dz < 3; dz++) {
                uint32_t ah[2][4], al[2][4], bhv[2][4], blv[2][4];
                uint32_t ab = sb + ks * (16 * A_STRIDE) + (wm * 32 + dz * 16) * 2 + aoff;
                LDSM4T(ah[0], ab);
                LDSM4T(ah[1], ab + 32);
                LDSM4T(al[0], ab + OFF_A_LO);
                LDSM4T(al[1], ab + OFF_A_LO + 32);
                uint32_t bb = sb + OFF_B + (dz * 2) * B_BLK + (wn * 32) * B_STRIDE
                            + ks * 32 + boff;
                LDSM4(bhv[0], bb);
                LDSM4(bhv[1], bb + 16 * B_STRIDE);
                LDSM4(blv[0], bb + B_BLK);
                LDSM4(blv[1], bb + B_BLK + 16 * B_STRIDE);
#pragma unroll
                for (int mi = 0; mi < 2; mi++)
#pragma unroll
                    for (int nj = 0; nj < 4; nj++) {
                        uint32_t* bp = &bhv[nj >> 1][(nj & 1) * 2];
                        uint32_t* lq = &blv[nj >> 1][(nj & 1) * 2];
                        MMA16816(d[mi][nj], ah[mi], bp[0], bp[1]);   // hi*hi
                        MMA16816(d[mi][nj], ah[mi], lq[0], lq[1]);   // hi*lo
                        MMA16816(d[mi][nj], al[mi], bp[0], bp[1]);   // lo*hi
                    }
            }
        }
    }

    // ---- epilogue: transpose through SMEM, coalesced float4 stores ----
    __syncthreads();
    float* sf = (float*)smem;                  // [co][132] f32
#pragma unroll
    for (int mi = 0; mi < 2; mi++)
#pragma unroll
        for (int nj = 0; nj < 4; nj++) {
            int r = l >> 2, c = (l & 3) * 2;
            int m0 = wm * 32 + mi * 16;
            int co = wn * 32 + nj * 8 + c;
            sf[co * 132 + m0 + r]           = d[mi][nj][0];
            sf[(co + 1) * 132 + m0 + r]     = d[mi][nj][1];
            sf[co * 132 + m0 + r + 8]       = d[mi][nj][2];
            sf[(co + 1) * 132 + m0 + r + 8] = d[mi][nj][3];
        }
    __syncthreads();
    const int pbase = (t * 16 + y) * 256 + h * 128;
    for (int q = tid; q < 2048; q += 256) {
        int co = q >> 5, c = (q & 31) * 4;
        float4 v = *(float4*)&sf[co * 132 + c];
        float bv = __ldg(bias + co);
        v.x += bv; v.y += bv; v.z += bv; v.w += bv;
        *(float4*)(out + (((size_t)(b * 64 + co)) << 16) + pbase + c) = v;
    }
}

extern "C" void kernel_launch(void* const* d_in, const int* in_sizes, int n_in,
                              void* d_out, int out_size) {
    const float* x    = (const float*)d_in[0];
    const float* wt   = (const float*)d_in[1];
    const float* bias = (const float*)d_in[2];
    float* out        = (float*)d_out;

    cudaFuncSetAttribute(conv4d_mma, cudaFuncAttributeMaxDynamicSharedMemorySize, SMEM_BYTES);
    prep_B<<<108, 256>>>(wt);
    conv4d_mma<<<2048, 256, SMEM_BYTES>>>(x, bias, out);
}

// round 6
// speedup vs baseline: 3.5404x; 1.2902x over previous
#include <cuda_runtime.h>
#include <cuda_bf16.h>
#include <cstdint>

// ============================================================================
// 4D circular conv (3^4), implicit GEMM on mma.sync.m16n8k16.bf16, hi/lo
// 3-chain split for fp32-grade accuracy (rel_err ~2e-5).
//
// R6: 4 ci-chunks of 16 (36 phases) -> SMEM 73.5KB -> 2 CTAs/SM, so one CTA's
// MMAs hide the other CTA's staging (tensor pipe was 53% busy at 1 CTA/SM).
//
// Per block (b,t,y,h): D[M=128 pos (8z x 16w), N=64 co] in registers.
// K folds (ci=16, dw=3) -> 48/phase; dz = row offset into z-haloed A slab.
// A in SMEM m-major [k][m] (ldmatrix.trans), B [co][k] (ldmatrix non-trans).
// ============================================================================

#define A_STRIDE 336      // bytes per k-row (168 bf16; 160 used) -> conflict-free
#define A_SZ     16128    // 48 * 336
#define OFF_A_LO 16128
#define OFF_B    32256
#define B_STRIDE 112      // bytes per co-row (56 bf16; 48 used) -> conflict-free
#define B_BLK    7168     // 64 * 112
#define SMEM_BYTES 75264  // OFF_B + 6*B_BLK
#define POS 65536

__device__ __forceinline__ uint32_t smem_u32(const void* p) {
    uint32_t a;
    asm("{ .reg .u64 t; cvta.to.shared.u64 t, %1; cvt.u32.u64 %0, t; }" : "=r"(a) : "l"(p));
    return a;
}

#define LDSM4(R, ADDR) \
    asm volatile("ldmatrix.sync.aligned.m8n8.x4.shared.b16 {%0,%1,%2,%3}, [%4];" \
        : "=r"((R)[0]), "=r"((R)[1]), "=r"((R)[2]), "=r"((R)[3]) : "r"(ADDR))
#define LDSM4T(R, ADDR) \
    asm volatile("ldmatrix.sync.aligned.m8n8.x4.trans.shared.b16 {%0,%1,%2,%3}, [%4];" \
        : "=r"((R)[0]), "=r"((R)[1]), "=r"((R)[2]), "=r"((R)[3]) : "r"(ADDR))
#define MMA16816(D, A, B0, B1) \
    asm volatile("mma.sync.aligned.m16n8k16.row.col.f32.bf16.bf16.f32 " \
        "{%0,%1,%2,%3}, {%4,%5,%6,%7}, {%8,%9}, {%0,%1,%2,%3};" \
        : "+f"((D)[0]), "+f"((D)[1]), "+f"((D)[2]), "+f"((D)[3]) \
        : "r"((A)[0]), "r"((A)[1]), "r"((A)[2]), "r"((A)[3]), "r"(B0), "r"(B1))

// ---- weight images: exact padded SMEM layout [co][k], per (tap,ver,chunk4) --
__device__ __align__(16) __nv_bfloat16 g_B[216 * 3584];   // 3584 = 64*56

__global__ void prep_B(const float* __restrict__ wt) {
    int nb = blockIdx.x;                       // (((i*3+dy)*3+dz)*2+ver)*4+chunk
    int chunk = nb & 3, ver = (nb >> 2) & 1, tap = nb >> 3;
    int dz = tap % 3, dy = (tap / 3) % 3, i = tap / 9;
    for (int e = threadIdx.x; e < 64 * 48; e += blockDim.x) {
        int co = e / 48, k = e - co * 48;      // k = cil*3 + dw
        int cil = k / 3, dw = k - cil * 3;
        int ci = chunk * 16 + cil;
        float w = wt[((i * 64 + co) * 64 + ci) * 27 + dy * 9 + dz * 3 + dw];
        __nv_bfloat16 hb = __float2bfloat16(w);
        __nv_bfloat16 vb = ver ? __float2bfloat16(w - __bfloat162float(hb)) : hb;
        g_B[nb * 3584 + co * 56 + k] = vb;
    }
}

// ---- main kernel ------------------------------------------------------------
__global__ __launch_bounds__(256, 2) void conv4d_mma(
    const float* __restrict__ x, const float* __restrict__ bias,
    float* __restrict__ out)
{
    extern __shared__ __align__(16) char smem[];
    const uint32_t sb = smem_u32(smem);
    const int tid = threadIdx.x;
    const int l = tid & 31, wid = tid >> 5;
    const int wm = wid & 3, wn = wid >> 2;     // warp tile: (wm*32 M, wn*32 N)

    const int bid = blockIdx.x;
    const int h = bid & 1;
    const int y = (bid >> 1) & 15;
    const int t = (bid >> 5) & 15;
    const int b = bid >> 9;

    const uint32_t aoff = ((l & 7) + ((l >> 4) & 1) * 8) * A_STRIDE + ((l >> 3) & 1) * 16;
    const uint32_t boff = ((l & 7) + ((l >> 4) & 1) * 8) * B_STRIDE + ((l >> 3) & 1) * 16;

    float d[2][4][4];
#pragma unroll
    for (int mi = 0; mi < 2; mi++)
#pragma unroll
        for (int nj = 0; nj < 4; nj++)
#pragma unroll
            for (int e = 0; e < 4; e++) d[mi][nj][e] = 0.f;

#pragma unroll 1
    for (int p = 0; p < 36; p++) {
        const int chunk = p & 3;
        const int idy9 = p >> 2;
        const int i = idy9 / 3, dy = idy9 - i * 3;
        const int tt = (t + i + 15) & 15;
        const int yy = (y + dy + 15) & 15;

        if (p > 0) __syncthreads();            // prior compute done reading SMEM

        // ---- stage A: 160 tasks (cil 16 x halo-z 10); hi/lo, 3 w-rotations ----
        for (int task = tid; task < 160; task += 256) {
            int cil = task / 10, r0 = task - cil * 10;
            int z_in = (8 * h + 15 + r0) & 15;
            const float4* src = (const float4*)(x +
                ((((b * 64 + chunk * 16 + cil) * 16 + tt) * 16 + yy) << 8) + z_in * 16);
            float v[16];
            *(float4*)(v)      = src[0];
            *(float4*)(v + 4)  = src[1];
            *(float4*)(v + 8)  = src[2];
            *(float4*)(v + 12) = src[3];
            uint32_t hp[8], lp[8];
#pragma unroll
            for (int j = 0; j < 8; j++) {
                float v0 = v[2 * j], v1 = v[2 * j + 1];
                __nv_bfloat16 h0 = __float2bfloat16(v0), h1 = __float2bfloat16(v1);
                __nv_bfloat16 l0 = __float2bfloat16(v0 - __bfloat162float(h0));
                __nv_bfloat16 l1 = __float2bfloat16(v1 - __bfloat162float(h1));
                hp[j] = (uint32_t)__bfloat16_as_ushort(h0) |
                        ((uint32_t)__bfloat16_as_ushort(h1) << 16);
                lp[j] = (uint32_t)__bfloat16_as_ushort(l0) |
                        ((uint32_t)__bfloat16_as_ushort(l1) << 16);
            }
            uint32_t h0r[8], h2r[8], l0r[8], l2r[8];   // rotations for dw=0 / dw=2
#pragma unroll
            for (int j = 0; j < 8; j++) {
                h0r[j] = __byte_perm(hp[(j + 7) & 7], hp[j], 0x5432);
                h2r[j] = __byte_perm(hp[j], hp[(j + 1) & 7], 0x5432);
                l0r[j] = __byte_perm(lp[(j + 7) & 7], lp[j], 0x5432);
                l2r[j] = __byte_perm(lp[j], lp[(j + 1) & 7], 0x5432);
            }
            char* bh = smem + (cil * 3) * A_STRIDE + r0 * 32;        // hi, k=cil*3
            char* bl = bh + OFF_A_LO;
            *(uint4*)(bh)                     = make_uint4(h0r[0], h0r[1], h0r[2], h0r[3]);
            *(uint4*)(bh + 16)                = make_uint4(h0r[4], h0r[5], h0r[6], h0r[7]);
            *(uint4*)(bh + A_STRIDE)          = make_uint4(hp[0], hp[1], hp[2], hp[3]);
            *(uint4*)(bh + A_STRIDE + 16)     = make_uint4(hp[4], hp[5], hp[6], hp[7]);
            *(uint4*)(bh + 2 * A_STRIDE)      = make_uint4(h2r[0], h2r[1], h2r[2], h2r[3]);
            *(uint4*)(bh + 2 * A_STRIDE + 16) = make_uint4(h2r[4], h2r[5], h2r[6], h2r[7]);
            *(uint4*)(bl)                     = make_uint4(l0r[0], l0r[1], l0r[2], l0r[3]);
            *(uint4*)(bl + 16)                = make_uint4(l0r[4], l0r[5], l0r[6], l0r[7]);
            *(uint4*)(bl + A_STRIDE)          = make_uint4(lp[0], lp[1], lp[2], lp[3]);
            *(uint4*)(bl + A_STRIDE + 16)     = make_uint4(lp[4], lp[5], lp[6], lp[7]);
            *(uint4*)(bl + 2 * A_STRIDE)      = make_uint4(l2r[0], l2r[1], l2r[2], l2r[3]);
            *(uint4*)(bl + 2 * A_STRIDE + 16) = make_uint4(l2r[4], l2r[5], l2r[6], l2r[7]);
        }

        // ---- stage B: 6 blocks x 7168B straight copy (slot = dz*2 + ver) ----
        {
            const int tapb = idy9 * 3;
            for (int q = tid; q < 6 * 448; q += 256) {
                int s = q / 448, r = q - s * 448;
                int dz = s >> 1, ver = s & 1;
                int nb = (((tapb + dz) * 2 + ver) << 2) + chunk;
                ((uint4*)(smem + OFF_B + s * B_BLK))[r] =
                    ((const uint4*)((const char*)g_B + (size_t)nb * B_BLK))[r];
            }
        }
        __syncthreads();

        // ---- compute: 3 k-steps x 3 dz x 3 chains x (2m x 4n) mma ----
#pragma unroll 1
        for (int ks = 0; ks < 3; ks++) {
#pragma unroll
            for (int dz = 0; dz < 3; dz++) {
                uint32_t ah[2][4], al[2][4], bhv[2][4], blv[2][4];
                uint32_t ab = sb + ks * (16 * A_STRIDE) + (wm * 32 + dz * 16) * 2 + aoff;
                LDSM4T(ah[0], ab);
                LDSM4T(ah[1], ab + 32);
                LDSM4T(al[0], ab + OFF_A_LO);
                LDSM4T(al[1], ab + OFF_A_LO + 32);
                uint32_t bb = sb + OFF_B + (dz * 2) * B_BLK + (wn * 32) * B_STRIDE
                            + ks * 32 + boff;
                LDSM4(bhv[0], bb);
                LDSM4(bhv[1], bb + 16 * B_STRIDE);
                LDSM4(blv[0], bb + B_BLK);
                LDSM4(blv[1], bb + B_BLK + 16 * B_STRIDE);
#pragma unroll
                for (int mi = 0; mi < 2; mi++)
#pragma unroll
                    for (int nj = 0; nj < 4; nj++) {
                        uint32_t* bp = &bhv[nj >> 1][(nj & 1) * 2];
                        uint32_t* lq = &blv[nj >> 1][(nj & 1) * 2];
                        MMA16816(d[mi][nj], ah[mi], bp[0], bp[1]);   // hi*hi
                        MMA16816(d[mi][nj], ah[mi], lq[0], lq[1]);   // hi*lo
                        MMA16816(d[mi][nj], al[mi], bp[0], bp[1]);   // lo*hi
                    }
            }
        }
    }

    // ---- epilogue: transpose through SMEM, coalesced float4 stores ----
    __syncthreads();
    float* sf = (float*)smem;                  // [co][132] f32
#pragma unroll
    for (int mi = 0; mi < 2; mi++)
#pragma unroll
        for (int nj = 0; nj < 4; nj++) {
            int r = l >> 2, c = (l & 3) * 2;
            int m0 = wm * 32 + mi * 16;
            int co = wn * 32 + nj * 8 + c;
            sf[co * 132 + m0 + r]           = d[mi][nj][0];
            sf[(co + 1) * 132 + m0 + r]     = d[mi][nj][1];
            sf[co * 132 + m0 + r + 8]       = d[mi][nj][2];
            sf[(co + 1) * 132 + m0 + r + 8] = d[mi][nj][3];
        }
    __syncthreads();
    const int pbase = (t * 16 + y) * 256 + h * 128;
    for (int q = tid; q < 2048; q += 256) {
        int co = q >> 5, c = (q & 31) * 4;
        float4 v = *(float4*)&sf[co * 132 + c];
        float bv = __ldg(bias + co);
        v.x += bv; v.y += bv; v.z += bv; v.w += bv;
        *(float4*)(out + (((size_t)(b * 64 + co)) << 16) + pbase + c) = v;
    }
}

extern "C" void kernel_launch(void* const* d_in, const int* in_sizes, int n_in,
                              void* d_out, int out_size) {
    const float* x    = (const float*)d_in[0];
    const float* wt   = (const float*)d_in[1];
    const float* bias = (const float*)d_in[2];
    float* out        = (float*)d_out;

    cudaFuncSetAttribute(conv4d_mma, cudaFuncAttributeMaxDynamicSharedMemorySize, SMEM_BYTES);
    prep_B<<<216, 256>>>(wt);
    conv4d_mma<<<2048, 256, SMEM_BYTES>>>(x, bias, out);
}